// round 15
// baseline (speedup 1.0000x reference)
#include <cuda_runtime.h>
#include <math.h>
#include <float.h>

// Problem dims
#define E_N      256
#define C_N      128
#define HW       3136          // 56*56
#define NC       200
#define NP       512
#define NL       64
#define LL       8
#define EDGE_DIM 256           // 2*C
#define LOOP_IN  258
#define FEAT     64

#define OUT_FULL_SIZE 49472

// ---------------- device scratch ----------------
__device__ float g_edge_x[E_N * EDGE_DIM];
__device__ float g_corner_feat[NC * EDGE_DIM];
__device__ __align__(16) float g_loop_feat[NL * FEAT];
__device__ float g_loop_conf[NL];
// transposed weights (lane = out-channel)
__device__ __align__(16) float g_Wep1T[EDGE_DIM * 64];
__device__ __align__(16) float g_WaggT[192 * C_N];
__device__ __align__(16) float g_Wc0T[LOOP_IN * 3 * 64];
__device__ __align__(16) float g_Wc1T[64 * 3 * 64];
__device__ __align__(16) float g_Wc2T[64 * 3 * 64];

// ---------------- fused pool (blocks 0..8191) + prep (blocks 8192..8255) --
__global__ void __launch_bounds__(128, 16) pool_prep_kernel(
        const float* __restrict__ image_x,
        const float* __restrict__ W_ep1,
        const float* __restrict__ W_agg,
        const float* __restrict__ Wc0,
        const float* __restrict__ Wc1,
        const float* __restrict__ Wc2,
        const float* __restrict__ coord_x) {
    if (blockIdx.x < 8192) {
        int gwarp = (blockIdx.x * 128 + threadIdx.x) >> 5;   // 0..32767
        int lane = threadIdx.x & 31;
        const float4* row = (const float4*)(image_x + (size_t)gwarp * HW);
        float m = -FLT_MAX;
        #pragma unroll 8
        for (int i = lane; i < 768; i += 32) {
            float4 v = row[i];
            m = fmaxf(m, fmaxf(fmaxf(v.x, v.y), fmaxf(v.z, v.w)));
        }
        if (lane < 16) {
            float4 v = row[768 + lane];
            m = fmaxf(m, fmaxf(fmaxf(v.x, v.y), fmaxf(v.z, v.w)));
        }
        #pragma unroll
        for (int o = 16; o; o >>= 1) m = fmaxf(m, __shfl_xor_sync(0xFFFFFFFFu, m, o));
        if (lane == 0) {
            int e = gwarp / C_N, c = gwarp % C_N;
            g_edge_x[e * EDGE_DIM + c] = m;
        }
    } else {
        int tid = (blockIdx.x - 8192) * 128 + threadIdx.x;
        const int stride = 64 * 128;
        for (int i = tid; i < EDGE_DIM * 64; i += stride) {
            int j = i >> 6, h = i & 63;
            g_Wep1T[i] = W_ep1[h * EDGE_DIM + j];
        }
        for (int i = tid; i < 192 * C_N; i += stride) {
            int j = i / C_N, c = i % C_N;
            g_WaggT[i] = W_agg[c * 192 + j];
        }
        for (int i = tid; i < LOOP_IN * 3 * 64; i += stride) {
            int ick = i >> 6, oc = i & 63;
            g_Wc0T[i] = Wc0[oc * (LOOP_IN * 3) + ick];
        }
        for (int i = tid; i < 64 * 3 * 64; i += stride) {
            int ick = i >> 6, oc = i & 63;
            g_Wc1T[i] = Wc1[oc * 192 + ick];
            g_Wc2T[i] = Wc2[oc * 192 + ick];
        }
        for (int i = tid; i < E_N * C_N; i += stride) {
            int e = i / C_N, c = i % C_N;
            g_edge_x[e * EDGE_DIM + C_N + c] = coord_x[i];
        }
    }
}

// ---------------- fused: edge confidence MLP + corner scatter-mean -------
__global__ void edge_corner_kernel(const int* __restrict__ pairs,
                                   const float* __restrict__ b_ep1,
                                   const float* __restrict__ W_ep2,
                                   const float* __restrict__ b_ep2,
                                   float* out_conf) {       // nullable
    __shared__ float s_f[256];
    __shared__ float s_part[256];
    __shared__ float sh[64];
    __shared__ int   s_list[NP];
    __shared__ int   s_n;
    int bid = blockIdx.x, t = threadIdx.x;

    if (bid < E_N) {
        if (!out_conf) return;
        s_f[t] = g_edge_x[bid * EDGE_DIM + t];
        __syncthreads();
        int h = t & 63, jc = t >> 6;
        float acc = 0.f;
        const float* w = g_Wep1T + (jc * 64) * 64;
        const float* x = s_f + jc * 64;
        #pragma unroll 8
        for (int j = 0; j < 64; j++) acc += w[j * 64 + h] * x[j];
        s_part[t] = acc;
        __syncthreads();
        if (t < 64) {
            float a = s_part[t] + s_part[64 + t] + s_part[128 + t] + s_part[192 + t] + b_ep1[t];
            sh[t] = fmaxf(a, 0.f) * W_ep2[t];
        }
        __syncthreads();
        if (t < 32) {
            float v = sh[t] + sh[t + 32];
            #pragma unroll
            for (int o = 16; o; o >>= 1) v += __shfl_xor_sync(0xFFFFFFFFu, v, o);
            if (t == 0) out_conf[bid] = 1.f / (1.f + expf(-(v + b_ep2[0])));
        }
    } else {
        int c = bid - E_N;
        if (t == 0) s_n = 0;
        __syncthreads();
        for (int p = t; p < NP; p += 256) {
            if (pairs[2 * p] == c) {
                int idx = atomicAdd(&s_n, 1);
                s_list[idx] = (p << 10) | pairs[2 * p + 1];
            }
        }
        __syncthreads();
        int n = s_n;
        if (t == 0 && n > 1) {
            for (int i = 1; i < n; i++) {
                int v = s_list[i], j = i - 1;
                while (j >= 0 && s_list[j] > v) { s_list[j + 1] = s_list[j]; j--; }
                s_list[j + 1] = v;
            }
        }
        __syncthreads();
        float acc = 0.f;
        for (int i = 0; i < n; i++)
            acc += g_edge_x[(s_list[i] & 1023) * EDGE_DIM + t];
        g_corner_feat[c * EDGE_DIM + t] = acc / fmaxf((float)n, 1.f);
    }
}

// ---------------- loop encoder v3: smem-staged weights -------------------
// 256 threads = 64 oc x 4 ic-chunks; weights tiled into smem (32 ic / tile)
__global__ void __launch_bounds__(256, 2) loopenc_kernel(
                               const int* __restrict__ loops,
                               const float* __restrict__ corners_xy,
                               const float* __restrict__ bc0,
                               const float* __restrict__ bc1,
                               const float* __restrict__ bc2,
                               const float* __restrict__ Wl1,
                               const float* __restrict__ bl1,
                               const float* __restrict__ Wl2,
                               const float* __restrict__ bl2,
                               float* out_loopconf) {       // nullable
    __shared__ float s_a[LOOP_IN * 10];   // input; aliased as s_red after conv reads
    __shared__ float s_b[64 * 10];
    __shared__ float s_c[64 * 10];
    __shared__ float s_w[32 * 3 * 64];    // weight tile (24 KB)
    __shared__ float s_lf[64];
    __shared__ int   s_cid[LL];
    float* s_red = s_a;                    // alias: 2048 <= 2580
    int nl = blockIdx.x, t = threadIdx.x;
    if (t < LL) s_cid[t] = loops[nl * LL + t];
    __syncthreads();
    // padded input [258][10]: pos 0 = x[1], pos 1..8 = x[0..7], pos 9 = x[6]
    for (int i = t; i < LOOP_IN * LL; i += 256) {
        int l = i / LOOP_IN, ch = i % LOOP_IN;
        int cid = s_cid[l];
        float v = (ch < EDGE_DIM) ? g_corner_feat[cid * EDGE_DIM + ch]
                                  : corners_xy[cid * 2 + (ch - EDGE_DIM)];
        s_a[ch * 10 + l + 1] = v;
    }
    __syncthreads();
    for (int ch = t; ch < LOOP_IN; ch += 256) {
        s_a[ch * 10]     = s_a[ch * 10 + 2];
        s_a[ch * 10 + 9] = s_a[ch * 10 + 7];
    }

    int oc = t & 63, grp = t >> 6;

    // ---- conv0: 258 -> 64, tiles of 32 ic ----
    float a[8] = {0,0,0,0,0,0,0,0};
    for (int ic0 = 0; ic0 < LOOP_IN; ic0 += 32) {
        int tsz = (LOOP_IN - ic0 < 32) ? (LOOP_IN - ic0) : 32;
        __syncthreads();   // prior tile readers done / input build done
        for (int i = t; i < tsz * 48; i += 256)
            ((float4*)s_w)[i] = ((const float4*)g_Wc0T)[ic0 * 48 + i];
        __syncthreads();
        for (int il = grp; il < tsz; il += 4) {
            int ic = ic0 + il;
            float r[10];
            #pragma unroll
            for (int q = 0; q < 10; q++) r[q] = s_a[ic * 10 + q];
            #pragma unroll
            for (int k = 0; k < 3; k++) {
                float w = s_w[(il * 3 + k) * 64 + oc];
                #pragma unroll
                for (int l = 0; l < 8; l++) a[l] += w * r[l + k];
            }
        }
    }
    __syncthreads();   // all s_a reads done before aliased s_red writes
    #pragma unroll
    for (int l = 0; l < 8; l++) s_red[(grp * 64 + oc) * 8 + l] = a[l];
    __syncthreads();
    for (int idx = t; idx < 512; idx += 256) {
        int o2 = idx >> 3, l = idx & 7;
        float v = s_red[(0 * 64 + o2) * 8 + l] + s_red[(1 * 64 + o2) * 8 + l]
                + s_red[(2 * 64 + o2) * 8 + l] + s_red[(3 * 64 + o2) * 8 + l] + bc0[o2];
        s_b[o2 * 10 + l + 1] = fmaxf(v, 0.f);
    }
    __syncthreads();
    if (t < 64) { s_b[t * 10] = s_b[t * 10 + 2]; s_b[t * 10 + 9] = s_b[t * 10 + 7]; }

    // ---- conv1: 64 -> 64, 2 tiles ----
    #pragma unroll
    for (int l = 0; l < 8; l++) a[l] = 0.f;
    for (int ic0 = 0; ic0 < 64; ic0 += 32) {
        __syncthreads();
        for (int i = t; i < 32 * 48; i += 256)
            ((float4*)s_w)[i] = ((const float4*)g_Wc1T)[ic0 * 48 + i];
        __syncthreads();
        for (int il = grp; il < 32; il += 4) {
            int ic = ic0 + il;
            float r[10];
            #pragma unroll
            for (int q = 0; q < 10; q++) r[q] = s_b[ic * 10 + q];
            #pragma unroll
            for (int k = 0; k < 3; k++) {
                float w = s_w[(il * 3 + k) * 64 + oc];
                #pragma unroll
                for (int l = 0; l < 8; l++) a[l] += w * r[l + k];
            }
        }
    }
    __syncthreads();
    #pragma unroll
    for (int l = 0; l < 8; l++) s_red[(grp * 64 + oc) * 8 + l] = a[l];
    __syncthreads();
    for (int idx = t; idx < 512; idx += 256) {
        int o2 = idx >> 3, l = idx & 7;
        float v = s_red[(0 * 64 + o2) * 8 + l] + s_red[(1 * 64 + o2) * 8 + l]
                + s_red[(2 * 64 + o2) * 8 + l] + s_red[(3 * 64 + o2) * 8 + l] + bc1[o2];
        s_c[o2 * 10 + l + 1] = fmaxf(v, 0.f);
    }
    __syncthreads();
    if (t < 64) { s_c[t * 10] = s_c[t * 10 + 2]; s_c[t * 10 + 9] = s_c[t * 10 + 7]; }

    // ---- conv2: 64 -> 64, fused relu + max over positions ----
    #pragma unroll
    for (int l = 0; l < 8; l++) a[l] = 0.f;
    for (int ic0 = 0; ic0 < 64; ic0 += 32) {
        __syncthreads();
        for (int i = t; i < 32 * 48; i += 256)
            ((float4*)s_w)[i] = ((const float4*)g_Wc2T)[ic0 * 48 + i];
        __syncthreads();
        for (int il = grp; il < 32; il += 4) {
            int ic = ic0 + il;
            float r[10];
            #pragma unroll
            for (int q = 0; q < 10; q++) r[q] = s_c[ic * 10 + q];
            #pragma unroll
            for (int k = 0; k < 3; k++) {
                float w = s_w[(il * 3 + k) * 64 + oc];
                #pragma unroll
                for (int l = 0; l < 8; l++) a[l] += w * r[l + k];
            }
        }
    }
    __syncthreads();
    #pragma unroll
    for (int l = 0; l < 8; l++) s_red[(grp * 64 + oc) * 8 + l] = a[l];
    __syncthreads();
    if (t < 64) {
        float m = -FLT_MAX;
        #pragma unroll
        for (int l = 0; l < 8; l++) {
            float v = s_red[(0 * 64 + t) * 8 + l] + s_red[(1 * 64 + t) * 8 + l]
                    + s_red[(2 * 64 + t) * 8 + l] + s_red[(3 * 64 + t) * 8 + l] + bc2[t];
            m = fmaxf(m, v);
        }
        float lf = fmaxf(m, 0.f);
        g_loop_feat[nl * 64 + t] = lf;
        s_lf[t] = lf;
    }
    __syncthreads();
    if (t < 32) {
        float h = bl1[t];
        #pragma unroll 8
        for (int j = 0; j < 64; j++) h += Wl1[t * 64 + j] * s_lf[j];
        float v = fmaxf(h, 0.f) * Wl2[t];
        #pragma unroll
        for (int o = 16; o; o >>= 1) v += __shfl_xor_sync(0xFFFFFFFFu, v, o);
        if (t == 0) {
            float conf = 1.f / (1.f + expf(-(v + bl2[0])));
            g_loop_conf[nl] = conf;
            if (out_loopconf) out_loopconf[nl] = conf;
        }
    }
}

// ---------------- loop-edge + coord_feat + final conv, 8 edges per block --
// grid = 32, 256 threads. All operands staged in smem once per block.
#define EPB 8   // edges per block
__global__ void __launch_bounds__(256, 2) loopedge_final_kernel(
                                      const int* __restrict__ edge_corner,
                                      const int* __restrict__ loops,
                                      const float* __restrict__ coord_x,
                                      float* __restrict__ out,
                                      float* out_le) {      // nullable
    __shared__ int   s_loops[NL * LL];        // 2 KB
    __shared__ float s_conf[NL];
    __shared__ int   s_ab[EPB * 2];
    __shared__ float s_feat[NL * FEAT];       // 16 KB
    __shared__ float s_lw[EPB][NL];           // 2 KB
    __shared__ float s_xin[EPB][192];         // 6 KB  (coord | coord_feat)
    __shared__ float s_w[32 * C_N];           // 16 KB j-tile
    int e0 = blockIdx.x * EPB, t = threadIdx.x;

    // ---- stage shared inputs ----
    for (int i = t; i < NL * LL; i += 256) s_loops[i] = loops[i];
    if (t < NL) s_conf[t] = g_loop_conf[t];
    if (t < EPB * 2) s_ab[t] = edge_corner[e0 * 2 + t];
    for (int i = t; i < NL * FEAT / 4; i += 256)
        ((float4*)s_feat)[i] = ((const float4*)g_loop_feat)[i];
    // coord rows for the 8 edges: 8*128 floats
    for (int i = t; i < EPB * C_N; i += 256) {
        int e = i >> 7, c = i & 127;
        s_xin[e][c] = coord_x[(e0 + e) * C_N + c];
    }
    __syncthreads();

    // ---- incidence: 8 edges x 64 loops = 512 items ----
    for (int item = t; item < EPB * NL; item += 256) {
        int el = item >> 6, nl = item & 63;
        int a = s_ab[el * 2], b = s_ab[el * 2 + 1];
        const int* c = s_loops + nl * LL;
        bool hit = false;
        #pragma unroll
        for (int l = 0; l < LL; l++) {
            int cl = c[l];
            int cp = c[(l + LL - 1) & 7];
            int cn = c[(l + 1) & 7];
            if (a == cl && (b == cp || b == cn)) hit = true;
        }
        float le = hit ? 1.f : 0.f;
        if (out_le) out_le[nl * E_N + e0 + el] = le;
        s_lw[el][nl] = le * s_conf[nl];
    }
    __syncthreads();

    // ---- coord_feat: thread = f(64) x group(4); each group does 2 edges ----
    {
        int f = t & 63, g = t >> 6;
        #pragma unroll
        for (int ee = 0; ee < 2; ee++) {
            int el = g * 2 + ee;
            float num = 0.f, den = 0.f;
            #pragma unroll 8
            for (int nl = 0; nl < NL; nl++) {
                float w = s_lw[el][nl];
                den += w;
                num += w * s_feat[nl * FEAT + f];
            }
            s_xin[el][C_N + f] = num / fmaxf(den, 1e-4f);
        }
    }

    // ---- final conv: thread = c(128) x eg(2); 4 edges per thread, all 192 j ----
    int c = t & 127, eg = t >> 7;
    float acc0 = 0.f, acc1 = 0.f, acc2 = 0.f, acc3 = 0.f;
    for (int tj = 0; tj < 6; tj++) {
        __syncthreads();   // prior tile reads done (also closes coord_feat writes on tj=0)
        for (int i = t; i < 32 * C_N / 4; i += 256)
            ((float4*)s_w)[i] = ((const float4*)g_WaggT)[tj * (32 * C_N / 4) + i];
        __syncthreads();
        int jbase = tj * 32;
        #pragma unroll 8
        for (int jj = 0; jj < 32; jj++) {
            float w = s_w[jj * C_N + c];
            int j = jbase + jj;
            acc0 += w * s_xin[eg * 4 + 0][j];
            acc1 += w * s_xin[eg * 4 + 1][j];
            acc2 += w * s_xin[eg * 4 + 2][j];
            acc3 += w * s_xin[eg * 4 + 3][j];
        }
    }
    out[(e0 + eg * 4 + 0) * C_N + c] = fmaxf(acc0, 0.f);
    out[(e0 + eg * 4 + 1) * C_N + c] = fmaxf(acc1, 0.f);
    out[(e0 + eg * 4 + 2) * C_N + c] = fmaxf(acc2, 0.f);
    out[(e0 + eg * 4 + 3) * C_N + c] = fmaxf(acc3, 0.f);
}

// ---------------- launch ---------------------------------------------------
extern "C" void kernel_launch(void* const* d_in, const int* in_sizes, int n_in,
                              void* d_out, int out_size) {
    const float* image_x     = (const float*)d_in[0];
    const float* coord_x     = (const float*)d_in[1];
    const float* corners     = (const float*)d_in[2];
    const int*   cep         = (const int*)  d_in[3];
    const int*   edge_corner = (const int*)  d_in[4];
    const int*   loops       = (const int*)  d_in[5];
    const float* W_ep1 = (const float*)d_in[6];
    const float* b_ep1 = (const float*)d_in[7];
    const float* W_ep2 = (const float*)d_in[8];
    const float* b_ep2 = (const float*)d_in[9];
    const float* Wc0   = (const float*)d_in[10];
    const float* bc0   = (const float*)d_in[11];
    const float* Wc1   = (const float*)d_in[12];
    const float* bc1   = (const float*)d_in[13];
    const float* Wc2   = (const float*)d_in[14];
    const float* bc2   = (const float*)d_in[15];
    const float* Wl1   = (const float*)d_in[16];
    const float* bl1   = (const float*)d_in[17];
    const float* Wl2   = (const float*)d_in[18];
    const float* bl2   = (const float*)d_in[19];
    const float* W_agg = (const float*)d_in[20];

    float* out = (float*)d_out;
    float* p_econf = nullptr;
    float* p_lconf = nullptr;
    float* p_le    = nullptr;
    if (out_size >= OUT_FULL_SIZE) {
        p_econf = out + E_N * C_N;
        p_lconf = p_econf + E_N;
        p_le    = p_lconf + NL;
    }

    pool_prep_kernel<<<8256, 128>>>(image_x, W_ep1, W_agg, Wc0, Wc1, Wc2, coord_x);
    edge_corner_kernel<<<E_N + NC, 256>>>(cep, b_ep1, W_ep2, b_ep2, p_econf);
    loopenc_kernel<<<NL, 256>>>(loops, corners, bc0, bc1, bc2,
                                Wl1, bl1, Wl2, bl2, p_lconf);
    loopedge_final_kernel<<<E_N / EPB, 256>>>(edge_corner, loops, coord_x, out, p_le);
}

// round 16
// speedup vs baseline: 1.0811x; 1.0811x over previous
#include <cuda_runtime.h>
#include <math.h>
#include <float.h>

// Problem dims
#define E_N      256
#define C_N      128
#define HW       3136          // 56*56
#define NC       200
#define NP       512
#define NL       64
#define LL       8
#define EDGE_DIM 256           // 2*C
#define LOOP_IN  258
#define FEAT     64

#define OUT_FULL_SIZE 49472

// ---------------- device scratch ----------------
__device__ float g_edge_x[E_N * EDGE_DIM];
__device__ float g_corner_feat[NC * EDGE_DIM];
__device__ __align__(16) float g_loop_feat[NL * FEAT];
__device__ float g_loop_conf[NL];
// transposed weights (lane = out-channel)
__device__ __align__(16) float g_Wep1T[EDGE_DIM * 64];
__device__ __align__(16) float g_WaggT[192 * C_N];
__device__ __align__(16) float g_Wc0T[LOOP_IN * 3 * 64];
__device__ __align__(16) float g_Wc1T[64 * 3 * 64];
__device__ __align__(16) float g_Wc2T[64 * 3 * 64];

// ---------------- fused pool (blocks 0..8191) + prep (blocks 8192..8255) --
__global__ void __launch_bounds__(128, 16) pool_prep_kernel(
        const float* __restrict__ image_x,
        const float* __restrict__ W_ep1,
        const float* __restrict__ W_agg,
        const float* __restrict__ Wc0,
        const float* __restrict__ Wc1,
        const float* __restrict__ Wc2,
        const float* __restrict__ coord_x) {
    if (blockIdx.x < 8192) {
        int gwarp = (blockIdx.x * 128 + threadIdx.x) >> 5;   // 0..32767
        int lane = threadIdx.x & 31;
        const float4* row = (const float4*)(image_x + (size_t)gwarp * HW);
        float m = -FLT_MAX;
        #pragma unroll 8
        for (int i = lane; i < 768; i += 32) {
            float4 v = row[i];
            m = fmaxf(m, fmaxf(fmaxf(v.x, v.y), fmaxf(v.z, v.w)));
        }
        if (lane < 16) {
            float4 v = row[768 + lane];
            m = fmaxf(m, fmaxf(fmaxf(v.x, v.y), fmaxf(v.z, v.w)));
        }
        #pragma unroll
        for (int o = 16; o; o >>= 1) m = fmaxf(m, __shfl_xor_sync(0xFFFFFFFFu, m, o));
        if (lane == 0) {
            int e = gwarp / C_N, c = gwarp % C_N;
            g_edge_x[e * EDGE_DIM + c] = m;
        }
    } else {
        int tid = (blockIdx.x - 8192) * 128 + threadIdx.x;
        const int stride = 64 * 128;
        for (int i = tid; i < EDGE_DIM * 64; i += stride) {
            int j = i >> 6, h = i & 63;
            g_Wep1T[i] = W_ep1[h * EDGE_DIM + j];
        }
        for (int i = tid; i < 192 * C_N; i += stride) {
            int j = i / C_N, c = i % C_N;
            g_WaggT[i] = W_agg[c * 192 + j];
        }
        for (int i = tid; i < LOOP_IN * 3 * 64; i += stride) {
            int ick = i >> 6, oc = i & 63;
            g_Wc0T[i] = Wc0[oc * (LOOP_IN * 3) + ick];
        }
        for (int i = tid; i < 64 * 3 * 64; i += stride) {
            int ick = i >> 6, oc = i & 63;
            g_Wc1T[i] = Wc1[oc * 192 + ick];
            g_Wc2T[i] = Wc2[oc * 192 + ick];
        }
        for (int i = tid; i < E_N * C_N; i += stride) {
            int e = i / C_N, c = i % C_N;
            g_edge_x[e * EDGE_DIM + C_N + c] = coord_x[i];
        }
    }
}

// ---------------- fused: edge confidence MLP + corner scatter-mean -------
__global__ void edge_corner_kernel(const int* __restrict__ pairs,
                                   const float* __restrict__ b_ep1,
                                   const float* __restrict__ W_ep2,
                                   const float* __restrict__ b_ep2,
                                   float* out_conf) {       // nullable
    __shared__ float s_f[256];
    __shared__ float s_part[256];
    __shared__ float sh[64];
    __shared__ int   s_list[NP];
    __shared__ int   s_n;
    int bid = blockIdx.x, t = threadIdx.x;

    if (bid < E_N) {
        if (!out_conf) return;
        s_f[t] = g_edge_x[bid * EDGE_DIM + t];
        __syncthreads();
        int h = t & 63, jc = t >> 6;
        float acc = 0.f;
        const float* w = g_Wep1T + (jc * 64) * 64;
        const float* x = s_f + jc * 64;
        #pragma unroll 8
        for (int j = 0; j < 64; j++) acc += w[j * 64 + h] * x[j];
        s_part[t] = acc;
        __syncthreads();
        if (t < 64) {
            float a = s_part[t] + s_part[64 + t] + s_part[128 + t] + s_part[192 + t] + b_ep1[t];
            sh[t] = fmaxf(a, 0.f) * W_ep2[t];
        }
        __syncthreads();
        if (t < 32) {
            float v = sh[t] + sh[t + 32];
            #pragma unroll
            for (int o = 16; o; o >>= 1) v += __shfl_xor_sync(0xFFFFFFFFu, v, o);
            if (t == 0) out_conf[bid] = 1.f / (1.f + expf(-(v + b_ep2[0])));
        }
    } else {
        int c = bid - E_N;
        if (t == 0) s_n = 0;
        __syncthreads();
        for (int p = t; p < NP; p += 256) {
            if (pairs[2 * p] == c) {
                int idx = atomicAdd(&s_n, 1);
                s_list[idx] = (p << 10) | pairs[2 * p + 1];
            }
        }
        __syncthreads();
        int n = s_n;
        if (t == 0 && n > 1) {
            for (int i = 1; i < n; i++) {
                int v = s_list[i], j = i - 1;
                while (j >= 0 && s_list[j] > v) { s_list[j + 1] = s_list[j]; j--; }
                s_list[j + 1] = v;
            }
        }
        __syncthreads();
        float acc = 0.f;
        for (int i = 0; i < n; i++)
            acc += g_edge_x[(s_list[i] & 1023) * EDGE_DIM + t];
        g_corner_feat[c * EDGE_DIM + t] = acc / fmaxf((float)n, 1.f);
    }
}

// ---------------- loop encoder v3: smem-staged weights -------------------
// 256 threads = 64 oc x 4 ic-chunks; weights tiled into smem (32 ic / tile)
__global__ void __launch_bounds__(256, 2) loopenc_kernel(
                               const int* __restrict__ loops,
                               const float* __restrict__ corners_xy,
                               const float* __restrict__ bc0,
                               const float* __restrict__ bc1,
                               const float* __restrict__ bc2,
                               const float* __restrict__ Wl1,
                               const float* __restrict__ bl1,
                               const float* __restrict__ Wl2,
                               const float* __restrict__ bl2,
                               float* out_loopconf) {       // nullable
    __shared__ float s_a[LOOP_IN * 10];   // input; aliased as s_red after conv reads
    __shared__ float s_b[64 * 10];
    __shared__ float s_c[64 * 10];
    __shared__ float s_w[32 * 3 * 64];    // weight tile (24 KB)
    __shared__ float s_lf[64];
    __shared__ int   s_cid[LL];
    float* s_red = s_a;                    // alias: 2048 <= 2580
    int nl = blockIdx.x, t = threadIdx.x;
    if (t < LL) s_cid[t] = loops[nl * LL + t];
    __syncthreads();
    // padded input [258][10]: pos 0 = x[1], pos 1..8 = x[0..7], pos 9 = x[6]
    for (int i = t; i < LOOP_IN * LL; i += 256) {
        int l = i / LOOP_IN, ch = i % LOOP_IN;
        int cid = s_cid[l];
        float v = (ch < EDGE_DIM) ? g_corner_feat[cid * EDGE_DIM + ch]
                                  : corners_xy[cid * 2 + (ch - EDGE_DIM)];
        s_a[ch * 10 + l + 1] = v;
    }
    __syncthreads();
    for (int ch = t; ch < LOOP_IN; ch += 256) {
        s_a[ch * 10]     = s_a[ch * 10 + 2];
        s_a[ch * 10 + 9] = s_a[ch * 10 + 7];
    }

    int oc = t & 63, grp = t >> 6;

    // ---- conv0: 258 -> 64, tiles of 32 ic ----
    float a[8] = {0,0,0,0,0,0,0,0};
    for (int ic0 = 0; ic0 < LOOP_IN; ic0 += 32) {
        int tsz = (LOOP_IN - ic0 < 32) ? (LOOP_IN - ic0) : 32;
        __syncthreads();   // prior tile readers done / input build done
        for (int i = t; i < tsz * 48; i += 256)
            ((float4*)s_w)[i] = ((const float4*)g_Wc0T)[ic0 * 48 + i];
        __syncthreads();
        for (int il = grp; il < tsz; il += 4) {
            int ic = ic0 + il;
            float r[10];
            #pragma unroll
            for (int q = 0; q < 10; q++) r[q] = s_a[ic * 10 + q];
            #pragma unroll
            for (int k = 0; k < 3; k++) {
                float w = s_w[(il * 3 + k) * 64 + oc];
                #pragma unroll
                for (int l = 0; l < 8; l++) a[l] += w * r[l + k];
            }
        }
    }
    __syncthreads();   // all s_a reads done before aliased s_red writes
    #pragma unroll
    for (int l = 0; l < 8; l++) s_red[(grp * 64 + oc) * 8 + l] = a[l];
    __syncthreads();
    for (int idx = t; idx < 512; idx += 256) {
        int o2 = idx >> 3, l = idx & 7;
        float v = s_red[(0 * 64 + o2) * 8 + l] + s_red[(1 * 64 + o2) * 8 + l]
                + s_red[(2 * 64 + o2) * 8 + l] + s_red[(3 * 64 + o2) * 8 + l] + bc0[o2];
        s_b[o2 * 10 + l + 1] = fmaxf(v, 0.f);
    }
    __syncthreads();
    if (t < 64) { s_b[t * 10] = s_b[t * 10 + 2]; s_b[t * 10 + 9] = s_b[t * 10 + 7]; }

    // ---- conv1: 64 -> 64, 2 tiles ----
    #pragma unroll
    for (int l = 0; l < 8; l++) a[l] = 0.f;
    for (int ic0 = 0; ic0 < 64; ic0 += 32) {
        __syncthreads();
        for (int i = t; i < 32 * 48; i += 256)
            ((float4*)s_w)[i] = ((const float4*)g_Wc1T)[ic0 * 48 + i];
        __syncthreads();
        for (int il = grp; il < 32; il += 4) {
            int ic = ic0 + il;
            float r[10];
            #pragma unroll
            for (int q = 0; q < 10; q++) r[q] = s_b[ic * 10 + q];
            #pragma unroll
            for (int k = 0; k < 3; k++) {
                float w = s_w[(il * 3 + k) * 64 + oc];
                #pragma unroll
                for (int l = 0; l < 8; l++) a[l] += w * r[l + k];
            }
        }
    }
    __syncthreads();
    #pragma unroll
    for (int l = 0; l < 8; l++) s_red[(grp * 64 + oc) * 8 + l] = a[l];
    __syncthreads();
    for (int idx = t; idx < 512; idx += 256) {
        int o2 = idx >> 3, l = idx & 7;
        float v = s_red[(0 * 64 + o2) * 8 + l] + s_red[(1 * 64 + o2) * 8 + l]
                + s_red[(2 * 64 + o2) * 8 + l] + s_red[(3 * 64 + o2) * 8 + l] + bc1[o2];
        s_c[o2 * 10 + l + 1] = fmaxf(v, 0.f);
    }
    __syncthreads();
    if (t < 64) { s_c[t * 10] = s_c[t * 10 + 2]; s_c[t * 10 + 9] = s_c[t * 10 + 7]; }

    // ---- conv2: 64 -> 64, fused relu + max over positions ----
    #pragma unroll
    for (int l = 0; l < 8; l++) a[l] = 0.f;
    for (int ic0 = 0; ic0 < 64; ic0 += 32) {
        __syncthreads();
        for (int i = t; i < 32 * 48; i += 256)
            ((float4*)s_w)[i] = ((const float4*)g_Wc2T)[ic0 * 48 + i];
        __syncthreads();
        for (int il = grp; il < 32; il += 4) {
            int ic = ic0 + il;
            float r[10];
            #pragma unroll
            for (int q = 0; q < 10; q++) r[q] = s_c[ic * 10 + q];
            #pragma unroll
            for (int k = 0; k < 3; k++) {
                float w = s_w[(il * 3 + k) * 64 + oc];
                #pragma unroll
                for (int l = 0; l < 8; l++) a[l] += w * r[l + k];
            }
        }
    }
    __syncthreads();
    #pragma unroll
    for (int l = 0; l < 8; l++) s_red[(grp * 64 + oc) * 8 + l] = a[l];
    __syncthreads();
    if (t < 64) {
        float m = -FLT_MAX;
        #pragma unroll
        for (int l = 0; l < 8; l++) {
            float v = s_red[(0 * 64 + t) * 8 + l] + s_red[(1 * 64 + t) * 8 + l]
                    + s_red[(2 * 64 + t) * 8 + l] + s_red[(3 * 64 + t) * 8 + l] + bc2[t];
            m = fmaxf(m, v);
        }
        float lf = fmaxf(m, 0.f);
        g_loop_feat[nl * 64 + t] = lf;
        s_lf[t] = lf;
    }
    __syncthreads();
    if (t < 32) {
        float h = bl1[t];
        #pragma unroll 8
        for (int j = 0; j < 64; j++) h += Wl1[t * 64 + j] * s_lf[j];
        float v = fmaxf(h, 0.f) * Wl2[t];
        #pragma unroll
        for (int o = 16; o; o >>= 1) v += __shfl_xor_sync(0xFFFFFFFFu, v, o);
        if (t == 0) {
            float conf = 1.f / (1.f + expf(-(v + bl2[0])));
            g_loop_conf[nl] = conf;
            if (out_loopconf) out_loopconf[nl] = conf;
        }
    }
}

// ---------------- loop-edge + coord_feat + final conv: v3 -----------------
// grid = 256 (block per edge), 512 threads; fine-grained splits, no bulk staging.
__global__ void __launch_bounds__(512) loopedge_final_kernel(
                                      const int* __restrict__ edge_corner,
                                      const int* __restrict__ loops,
                                      const float* __restrict__ coord_x,
                                      float* __restrict__ out,
                                      float* out_le) {      // nullable
    __shared__ int   s_loops[NL * LL];   // 2 KB
    __shared__ float s_lw[NL];
    __shared__ float sx[192];
    __shared__ float s_num[512];
    __shared__ float s_den[512];
    int e = blockIdx.x, t = threadIdx.x;
    for (int i = t; i < NL * LL; i += 512) s_loops[i] = loops[i];
    if (t < C_N) sx[t] = coord_x[e * C_N + t];
    int a = edge_corner[2 * e], b = edge_corner[2 * e + 1];
    __syncthreads();
    if (t < NL) {
        const int* c = s_loops + t * LL;
        bool hit = false;
        #pragma unroll
        for (int l = 0; l < LL; l++) {
            int cl = c[l];
            int cp = c[(l + LL - 1) & 7];
            int cn = c[(l + 1) & 7];
            if (a == cl && (b == cp || b == cn)) hit = true;
        }
        float le = hit ? 1.f : 0.f;
        if (out_le) out_le[t * E_N + e] = le;
        s_lw[t] = le * g_loop_conf[t];
    }
    __syncthreads();
    // coord_feat: f(64) x g(8); each g handles 8 nls (coalesced g_loop_feat reads)
    {
        int f = t & 63, g = t >> 6;
        float num = 0.f, den = 0.f;
        #pragma unroll
        for (int nl = g * 8; nl < g * 8 + 8; nl++) {
            float w = s_lw[nl];
            den += w;
            num += w * g_loop_feat[nl * FEAT + f];
        }
        s_num[t] = num; s_den[t] = den;
    }
    __syncthreads();
    if (t < 64) {
        float nn = 0.f, dd = 0.f;
        #pragma unroll
        for (int g = 0; g < 8; g++) { nn += s_num[g * 64 + t]; dd += s_den[g * 64 + t]; }
        sx[C_N + t] = nn / fmaxf(dd, 1e-4f);
    }
    __syncthreads();
    // final conv: c(128) x jc(4) of 48 j each; coalesced g_WaggT reads
    int c = t & 127, jc = t >> 7;
    float acc = 0.f;
    const float* w = g_WaggT + (jc * 48) * C_N;
    const float* x = sx + jc * 48;
    #pragma unroll 8
    for (int j = 0; j < 48; j++) acc += w[j * C_N + c] * x[j];
    s_num[t] = acc;
    __syncthreads();
    if (t < C_N)
        out[e * C_N + t] = fmaxf(s_num[t] + s_num[128 + t] + s_num[256 + t] + s_num[384 + t], 0.f);
}

// ---------------- launch ---------------------------------------------------
extern "C" void kernel_launch(void* const* d_in, const int* in_sizes, int n_in,
                              void* d_out, int out_size) {
    const float* image_x     = (const float*)d_in[0];
    const float* coord_x     = (const float*)d_in[1];
    const float* corners     = (const float*)d_in[2];
    const int*   cep         = (const int*)  d_in[3];
    const int*   edge_corner = (const int*)  d_in[4];
    const int*   loops       = (const int*)  d_in[5];
    const float* W_ep1 = (const float*)d_in[6];
    const float* b_ep1 = (const float*)d_in[7];
    const float* W_ep2 = (const float*)d_in[8];
    const float* b_ep2 = (const float*)d_in[9];
    const float* Wc0   = (const float*)d_in[10];
    const float* bc0   = (const float*)d_in[11];
    const float* Wc1   = (const float*)d_in[12];
    const float* bc1   = (const float*)d_in[13];
    const float* Wc2   = (const float*)d_in[14];
    const float* bc2   = (const float*)d_in[15];
    const float* Wl1   = (const float*)d_in[16];
    const float* bl1   = (const float*)d_in[17];
    const float* Wl2   = (const float*)d_in[18];
    const float* bl2   = (const float*)d_in[19];
    const float* W_agg = (const float*)d_in[20];

    float* out = (float*)d_out;
    float* p_econf = nullptr;
    float* p_lconf = nullptr;
    float* p_le    = nullptr;
    if (out_size >= OUT_FULL_SIZE) {
        p_econf = out + E_N * C_N;
        p_lconf = p_econf + E_N;
        p_le    = p_lconf + NL;
    }

    pool_prep_kernel<<<8256, 128>>>(image_x, W_ep1, W_agg, Wc0, Wc1, Wc2, coord_x);
    edge_corner_kernel<<<E_N + NC, 256>>>(cep, b_ep1, W_ep2, b_ep2, p_econf);
    loopenc_kernel<<<NL, 256>>>(loops, corners, bc0, bc1, bc2,
                                Wl1, bl1, Wl2, bl2, p_lconf);
    loopedge_final_kernel<<<E_N, 512>>>(edge_corner, loops, coord_x, out, p_le);
}